// round 1
// baseline (speedup 1.0000x reference)
#include <cuda_runtime.h>
#include <math.h>

// Problem constants
#define BATCH 4
#define SEQ   4096
#define HID   1024
#define NH    16
#define DH    64
#define M_TOT (BATCH * SEQ)   // 16384
#define N_TOT (3 * HID)       // 3072
#define K_TOT HID             // 1024

// Scratch for qkv projection result: 16384 x 3072 fp32 = 192 MB (static device global)
__device__ float g_qkv[(size_t)M_TOT * N_TOT];

// ---------------------------------------------------------------------------
// GEMM: C[m,n] = sum_k A[m,k] * W[n,k] + bias[n]
// A: (16384, 1024) row-major, W: (3072, 1024) row-major ("NT" gemm — both K-contig)
// Tile: BM=128, BN=128, BK=8, 256 threads, 8x8 per-thread micro-tile.
// ---------------------------------------------------------------------------
#define BM 128
#define BN 128
#define BK 8

__global__ __launch_bounds__(256) void gemm_qkv_kernel(
    const float* __restrict__ A, const float* __restrict__ W,
    const float* __restrict__ bias, float* __restrict__ C)
{
    __shared__ float As[BK][BM];
    __shared__ float Bs[BK][BN];

    const int t  = threadIdx.x;      // 0..255
    const int tx = t & 15;           // n-direction: 16 threads * 8 cols = 128
    const int ty = t >> 4;           // m-direction: 16 threads * 8 rows = 128
    const int m0 = blockIdx.y * BM;
    const int n0 = blockIdx.x * BN;

    float acc[8][8];
#pragma unroll
    for (int i = 0; i < 8; i++)
#pragma unroll
        for (int j = 0; j < 8; j++) acc[i][j] = 0.0f;

    // Each thread loads one float4 of A-tile and one of B-tile per k-step.
    // Tile is 128 rows x 8 k = 256 float4 → exactly one per thread.
    const int lrow = t >> 1;          // 0..127
    const int lk4  = (t & 1) * 4;     // 0 or 4

    const float* Aptr = A + (size_t)(m0 + lrow) * K_TOT + lk4;
    const float* Wptr = W + (size_t)(n0 + lrow) * K_TOT + lk4;

    for (int k0 = 0; k0 < K_TOT; k0 += BK) {
        const float4 av = *(const float4*)(Aptr + k0);
        const float4 bv = *(const float4*)(Wptr + k0);
        As[lk4 + 0][lrow] = av.x;
        As[lk4 + 1][lrow] = av.y;
        As[lk4 + 2][lrow] = av.z;
        As[lk4 + 3][lrow] = av.w;
        Bs[lk4 + 0][lrow] = bv.x;
        Bs[lk4 + 1][lrow] = bv.y;
        Bs[lk4 + 2][lrow] = bv.z;
        Bs[lk4 + 3][lrow] = bv.w;
        __syncthreads();

#pragma unroll
        for (int k = 0; k < BK; k++) {
            const float4 a0 = *(const float4*)&As[k][ty * 8 + 0];
            const float4 a1 = *(const float4*)&As[k][ty * 8 + 4];
            const float4 b0 = *(const float4*)&Bs[k][tx * 8 + 0];
            const float4 b1 = *(const float4*)&Bs[k][tx * 8 + 4];
            const float a[8] = {a0.x, a0.y, a0.z, a0.w, a1.x, a1.y, a1.z, a1.w};
            const float b[8] = {b0.x, b0.y, b0.z, b0.w, b1.x, b1.y, b1.z, b1.w};
#pragma unroll
            for (int i = 0; i < 8; i++)
#pragma unroll
                for (int j = 0; j < 8; j++)
                    acc[i][j] += a[i] * b[j];
        }
        __syncthreads();
    }

    // Epilogue: add bias, write C (row stride N_TOT)
    float bb[8];
#pragma unroll
    for (int j = 0; j < 8; j++) bb[j] = bias[n0 + tx * 8 + j];

#pragma unroll
    for (int i = 0; i < 8; i++) {
        const int m = m0 + ty * 8 + i;
        float* crow = C + (size_t)m * N_TOT + n0 + tx * 8;
        float4 w0, w1;
        w0.x = acc[i][0] + bb[0]; w0.y = acc[i][1] + bb[1];
        w0.z = acc[i][2] + bb[2]; w0.w = acc[i][3] + bb[3];
        w1.x = acc[i][4] + bb[4]; w1.y = acc[i][5] + bb[5];
        w1.z = acc[i][6] + bb[6]; w1.w = acc[i][7] + bb[7];
        *(float4*)(crow + 0) = w0;
        *(float4*)(crow + 4) = w1;
    }
}

// ---------------------------------------------------------------------------
// Attention: one block per (b,s) position.
// q,k,v each (16 heads x 64). scores[h][g] = q[h]·k[g]/8 + mask[p,h,g];
// softmax over g; out[h] = sum_g w[h][g] * v[g].
// ---------------------------------------------------------------------------
__global__ __launch_bounds__(256) void attn_kernel(
    const float* __restrict__ qkv, const float* __restrict__ mask,
    float* __restrict__ out)
{
    __shared__ float sq[HID];
    __shared__ float sk[HID];
    __shared__ float sv[HID];
    __shared__ float sw[NH][NH];
    __shared__ float srmax[NH];
    __shared__ float srsuminv[NH];

    const int p = blockIdx.x;            // position in [0, B*S)
    const int t = threadIdx.x;           // 0..255

    // Load q,k,v (3072 floats = 768 float4; 256 threads x 3)
    {
        const float4* src = (const float4*)(qkv + (size_t)p * N_TOT);
        ((float4*)sq)[t] = src[t];
        ((float4*)sk)[t] = src[256 + t];
        ((float4*)sv)[t] = src[512 + t];
    }
    __syncthreads();

    // Scores: thread (h,g) computes one 64-length dot product
    const int h = t >> 4;
    const int g = t & 15;
    {
        const float* qh = sq + h * DH;
        const float* kg = sk + g * DH;
        float s = 0.0f;
#pragma unroll
        for (int d = 0; d < DH; d++) s += qh[d] * kg[d];
        s = s * 0.125f + mask[(size_t)p * (NH * NH) + t];
        sw[h][g] = s;
    }
    __syncthreads();

    // Per-row max and sum-of-exp (16 rows handled serially by 16 threads)
    if (t < NH) {
        float mx = -INFINITY;
#pragma unroll
        for (int j = 0; j < NH; j++) mx = fmaxf(mx, sw[t][j]);
        float sum = 0.0f;
#pragma unroll
        for (int j = 0; j < NH; j++) sum += expf(sw[t][j] - mx);
        srmax[t] = mx;
        srsuminv[t] = 1.0f / sum;
    }
    __syncthreads();

    // Normalized weights back into sw
    const float w = expf(sw[h][g] - srmax[h]) * srsuminv[h];
    __syncthreads();
    sw[h][g] = w;
    __syncthreads();

    // Output: thread t computes out[h, d0..d0+3] where d0 = (t&15)*4
    const int d0 = (t & 15) * 4;
    float4 acc = make_float4(0.f, 0.f, 0.f, 0.f);
#pragma unroll
    for (int gg = 0; gg < NH; gg++) {
        const float wv = sw[h][gg];
        const float4 v4 = *(const float4*)(sv + gg * DH + d0);
        acc.x += wv * v4.x;
        acc.y += wv * v4.y;
        acc.z += wv * v4.z;
        acc.w += wv * v4.w;
    }
    *(float4*)(out + (size_t)p * HID + h * DH + d0) = acc;
}

// ---------------------------------------------------------------------------
// Launch
// inputs (metadata order): 0=query, 1=key, 2=value, 3=attn_mask, 4=W_qkv, 5=b_qkv
// ---------------------------------------------------------------------------
extern "C" void kernel_launch(void* const* d_in, const int* in_sizes, int n_in,
                              void* d_out, int out_size)
{
    const float* query = (const float*)d_in[0];
    const float* mask  = (const float*)d_in[3];
    const float* W     = (const float*)d_in[4];
    const float* bias  = (const float*)d_in[5];
    float* out = (float*)d_out;

    float* qkv;
    cudaGetSymbolAddress((void**)&qkv, g_qkv);

    dim3 ggrid(N_TOT / BN, M_TOT / BM);   // (24, 128)
    gemm_qkv_kernel<<<ggrid, 256>>>(query, W, bias, qkv);

    attn_kernel<<<M_TOT, 256>>>(qkv, mask, out);
}

// round 3
// speedup vs baseline: 2.1696x; 2.1696x over previous
#include <cuda_runtime.h>
#include <cuda_bf16.h>
#include <cstdint>
#include <math.h>

// ---------------------------------------------------------------------------
// Problem constants
// ---------------------------------------------------------------------------
#define BATCH 4
#define SEQ   4096
#define HID   1024
#define NH    16
#define DH    64
#define M_TOT (BATCH * SEQ)   // 16384
#define N_TOT (3 * HID)       // 3072
#define K_TOT HID             // 1024

// Scratch (device globals: allocation-free rule)
__device__ float          g_qkv[(size_t)M_TOT * N_TOT];  // 192 MB
__device__ __nv_bfloat16  g_ah[(size_t)M_TOT * K_TOT];   // 32 MB
__device__ __nv_bfloat16  g_al[(size_t)M_TOT * K_TOT];   // 32 MB
__device__ __nv_bfloat16  g_wh[(size_t)N_TOT * K_TOT];   // 6 MB
__device__ __nv_bfloat16  g_wl[(size_t)N_TOT * K_TOT];   // 6 MB

// ---------------------------------------------------------------------------
// Helpers (all sm_80-era PTX — compiles under compute_103, no "a" features)
// ---------------------------------------------------------------------------
__device__ __forceinline__ uint32_t smem_u32(const void* p) {
    uint32_t a;
    asm("{ .reg .u64 t; cvta.to.shared.u64 t, %1; cvt.u32.u64 %0, t; }"
        : "=r"(a) : "l"(p));
    return a;
}

__device__ __forceinline__ void cp_async16(uint32_t s, const void* g) {
    asm volatile("cp.async.cg.shared.global [%0], [%1], 16;" :: "r"(s), "l"(g) : "memory");
}

__device__ __forceinline__ void ldsm_x4(uint32_t& r0, uint32_t& r1,
                                        uint32_t& r2, uint32_t& r3, uint32_t addr) {
    asm volatile("ldmatrix.sync.aligned.m8n8.x4.shared.b16 {%0,%1,%2,%3}, [%4];"
                 : "=r"(r0), "=r"(r1), "=r"(r2), "=r"(r3) : "r"(addr));
}

__device__ __forceinline__ void mma_bf16(float* c, const uint32_t* a,
                                         uint32_t b0, uint32_t b1) {
    asm volatile(
        "mma.sync.aligned.m16n8k16.row.col.f32.bf16.bf16.f32 "
        "{%0,%1,%2,%3}, {%4,%5,%6,%7}, {%8,%9}, {%0,%1,%2,%3};"
        : "+f"(c[0]), "+f"(c[1]), "+f"(c[2]), "+f"(c[3])
        : "r"(a[0]), "r"(a[1]), "r"(a[2]), "r"(a[3]), "r"(b0), "r"(b1));
}

// ---------------------------------------------------------------------------
// Conversion: fp32 -> (bf16 hi, bf16 lo) for A (=query) and W
// ---------------------------------------------------------------------------
#define N4_A ((size_t)M_TOT * K_TOT / 4)
#define N4_W ((size_t)N_TOT * K_TOT / 4)
#define N4_TOTAL (N4_A + N4_W)

__global__ __launch_bounds__(256) void convert_kernel(
    const float* __restrict__ A, const float* __restrict__ W)
{
    size_t idx = (size_t)blockIdx.x * blockDim.x + threadIdx.x;
    if (idx >= N4_TOTAL) return;

    const float4* src;
    __nv_bfloat16 *hi_out, *lo_out;
    size_t j;
    if (idx < N4_A) {
        src = (const float4*)A; j = idx; hi_out = g_ah; lo_out = g_al;
    } else {
        src = (const float4*)W; j = idx - N4_A; hi_out = g_wh; lo_out = g_wl;
    }
    float4 v = src[j];
    float f[4] = {v.x, v.y, v.z, v.w};
    __nv_bfloat16 h[4], l[4];
#pragma unroll
    for (int i = 0; i < 4; i++) {
        h[i] = __float2bfloat16_rn(f[i]);
        l[i] = __float2bfloat16_rn(f[i] - __bfloat162float(h[i]));
    }
    *(uint2*)(hi_out + j * 4) = *(uint2*)h;
    *(uint2*)(lo_out + j * 4) = *(uint2*)l;
}

// ---------------------------------------------------------------------------
// GEMM via mma.sync bf16x3: C[m,n] = sum_k A[m,k]*W[n,k] + bias[n]
// CTA tile 128x128, BK=32, 8 warps (warp tile 64x32), 3-stage cp.async.
// Smem rows padded to 80B -> conflict-free ldmatrix, 16B-aligned cp.async.
// ---------------------------------------------------------------------------
#define BK      32
#define KITERS  (K_TOT / BK)     // 32
#define STAGES  3
#define ROWB    80               // bytes per smem row (32 bf16 -> 40 elems)
#define TILEB   (128 * ROWB)     // 10240
#define STAGEB  (4 * TILEB)      // 40960
#define GEMM_SMEM (STAGES * STAGEB)  // 122880

__global__ void __launch_bounds__(256, 1) gemm_qkv_mma(
    const __nv_bfloat16* __restrict__ Ah, const __nv_bfloat16* __restrict__ Al,
    const __nv_bfloat16* __restrict__ Wh, const __nv_bfloat16* __restrict__ Wl,
    const float* __restrict__ bias, float* __restrict__ C)
{
    extern __shared__ char smem[];
    const uint32_t sb = smem_u32(smem);
    const int t    = threadIdx.x;
    const int wid  = t >> 5;
    const int lane = t & 31;
    const int m0 = blockIdx.y * 128;
    const int n0 = blockIdx.x * 128;
    const int wm = (wid & 1) * 64;   // warp m-offset within CTA tile
    const int wn = (wid >> 1) * 32;  // warp n-offset

    // ---- cp.async mapping: 8 x 16B chunks per thread per stage ----
    // i: tile = i>>1 (0=Ah,1=Al,2=Wh,3=Wl), sub = i&1 (row halves)
    const char* gptr[8];
    uint32_t    soff[8];
#pragma unroll
    for (int i = 0; i < 8; i++) {
        const int tile = i >> 1;
        const int row  = (i & 1) * 64 + (t >> 2);   // 0..127
        const int c    = t & 3;                     // 16B chunk in 64B row
        const __nv_bfloat16* base =
            (tile == 0) ? Ah : (tile == 1) ? Al : (tile == 2) ? Wh : Wl;
        const int grow = ((tile < 2) ? m0 : n0) + row;
        gptr[i] = (const char*)(base + (size_t)grow * K_TOT) + c * 16;
        soff[i] = (uint32_t)(tile * TILEB + row * ROWB + c * 16);
    }

    auto load_stage = [&](int s) {
        const uint32_t dst = sb + (s % STAGES) * STAGEB;
        const int koff = s * (BK * 2);  // 64 bytes per k-stage
#pragma unroll
        for (int i = 0; i < 8; i++)
            cp_async16(dst + soff[i], gptr[i] + koff);
    };

    float acc[4][4][4];
#pragma unroll
    for (int mt = 0; mt < 4; mt++)
#pragma unroll
        for (int nt = 0; nt < 4; nt++)
#pragma unroll
            for (int q = 0; q < 4; q++) acc[mt][nt][q] = 0.0f;

    // Prologue: fill all 3 stages
#pragma unroll
    for (int s = 0; s < STAGES; s++) {
        load_stage(s);
        asm volatile("cp.async.commit_group;" ::: "memory");
    }

    const int lrow  = lane & 15;
    const int lkoff = (lane >> 4) * 16;  // bytes: 8 bf16

    for (int kit = 0; kit < KITERS; kit++) {
        asm volatile("cp.async.wait_group %0;" :: "n"(STAGES - 1) : "memory");
        __syncthreads();

        const uint32_t bufb = sb + (kit % STAGES) * STAGEB;
        const uint32_t aHi = bufb;
        const uint32_t aLo = bufb + TILEB;
        const uint32_t wHi = bufb + 2 * TILEB;
        const uint32_t wLo = bufb + 3 * TILEB;

#pragma unroll
        for (int ks = 0; ks < 2; ks++) {
            const uint32_t kb = (uint32_t)(ks * 32 + lkoff);  // byte col offset

            uint32_t ah[4][4], al[4][4];
#pragma unroll
            for (int mt = 0; mt < 4; mt++) {
                const uint32_t ro = (uint32_t)((wm + mt * 16 + lrow) * ROWB) + kb;
                ldsm_x4(ah[mt][0], ah[mt][1], ah[mt][2], ah[mt][3], aHi + ro);
                ldsm_x4(al[mt][0], al[mt][1], al[mt][2], al[mt][3], aLo + ro);
            }

            // B frags: 4 n8-tiles, each {b0,b1}, for hi and lo
            uint32_t bh0[4], bh1[4], bl0[4], bl1[4];
#pragma unroll
            for (int np = 0; np < 2; np++) {
                const uint32_t ro = (uint32_t)((wn + np * 16 + lrow) * ROWB) + kb;
                uint32_t r0, r1, r2, r3;
                ldsm_x4(r0, r1, r2, r3, wHi + ro);
                bh0[np * 2] = r0; bh1[np * 2] = r2;
                bh0[np * 2 + 1] = r1; bh1[np * 2 + 1] = r3;
                ldsm_x4(r0, r1, r2, r3, wLo + ro);
                bl0[np * 2] = r0; bl1[np * 2] = r2;
                bl0[np * 2 + 1] = r1; bl1[np * 2 + 1] = r3;
            }

#pragma unroll
            for (int mt = 0; mt < 4; mt++) {
#pragma unroll
                for (int nt = 0; nt < 4; nt++) {
                    mma_bf16(acc[mt][nt], ah[mt], bh0[nt], bh1[nt]);  // Ah*Wh
                    mma_bf16(acc[mt][nt], al[mt], bh0[nt], bh1[nt]);  // Al*Wh
                    mma_bf16(acc[mt][nt], ah[mt], bl0[nt], bl1[nt]);  // Ah*Wl
                }
            }
        }

        __syncthreads();
        if (kit + STAGES < KITERS) load_stage(kit + STAGES);
        asm volatile("cp.async.commit_group;" ::: "memory");
    }

    // ---- Epilogue: bias add + store ----
#pragma unroll
    for (int mt = 0; mt < 4; mt++) {
        const int r = m0 + wm + mt * 16 + (lane >> 2);
#pragma unroll
        for (int nt = 0; nt < 4; nt++) {
            const int cc = n0 + wn + nt * 8 + (lane & 3) * 2;
            const float bx = __ldg(bias + cc);
            const float by = __ldg(bias + cc + 1);
            float2 v0, v1;
            v0.x = acc[mt][nt][0] + bx; v0.y = acc[mt][nt][1] + by;
            v1.x = acc[mt][nt][2] + bx; v1.y = acc[mt][nt][3] + by;
            *(float2*)(C + (size_t)r * N_TOT + cc)       = v0;
            *(float2*)(C + (size_t)(r + 8) * N_TOT + cc) = v1;
        }
    }
}

// ---------------------------------------------------------------------------
// Attention: one block per (b,s) position. Bank-conflict-free smem layouts.
// ---------------------------------------------------------------------------
__global__ __launch_bounds__(256) void attn_kernel(
    const float* __restrict__ qkv, const float* __restrict__ mask,
    float* __restrict__ out)
{
    __shared__ float sq[NH][DH + 1];
    __shared__ float sk[NH][DH + 1];
    __shared__ float sv[HID];
    __shared__ float sw[NH][17];
    __shared__ float srmax[NH];
    __shared__ float srsuminv[NH];

    const int p = blockIdx.x;
    const int t = threadIdx.x;

    {
        const float4* src = (const float4*)(qkv + (size_t)p * N_TOT);
        const int hh = t >> 4;
        const int dd = (t & 15) * 4;
        float4 a = src[t];
        sq[hh][dd + 0] = a.x; sq[hh][dd + 1] = a.y;
        sq[hh][dd + 2] = a.z; sq[hh][dd + 3] = a.w;
        float4 b = src[256 + t];
        sk[hh][dd + 0] = b.x; sk[hh][dd + 1] = b.y;
        sk[hh][dd + 2] = b.z; sk[hh][dd + 3] = b.w;
        ((float4*)sv)[t] = src[512 + t];
    }
    __syncthreads();

    const int h = t >> 4;
    const int g = t & 15;

    {
        float s = 0.0f;
#pragma unroll
        for (int d = 0; d < DH; d++) s += sq[h][d] * sk[g][d];
        s = s * 0.125f + __ldg(mask + (size_t)p * (NH * NH) + t);
        sw[h][g] = s;
    }
    __syncthreads();

    if (t < NH) {
        float mx = -INFINITY;
#pragma unroll
        for (int j = 0; j < NH; j++) mx = fmaxf(mx, sw[t][j]);
        float sum = 0.0f;
#pragma unroll
        for (int j = 0; j < NH; j++) sum += __expf(sw[t][j] - mx);
        srmax[t] = mx;
        srsuminv[t] = 1.0f / sum;
    }
    __syncthreads();

    const float w = __expf(sw[h][g] - srmax[h]) * srsuminv[h];
    __syncthreads();
    sw[h][g] = w;
    __syncthreads();

    const int d0 = (t & 15) * 4;
    float4 acc = make_float4(0.f, 0.f, 0.f, 0.f);
#pragma unroll
    for (int gg = 0; gg < NH; gg++) {
        const float wv = sw[h][gg];
        const float4 v4 = *(const float4*)(sv + gg * DH + d0);
        acc.x += wv * v4.x; acc.y += wv * v4.y;
        acc.z += wv * v4.z; acc.w += wv * v4.w;
    }
    *(float4*)(out + (size_t)p * HID + h * DH + d0) = acc;
}

// ---------------------------------------------------------------------------
// Launch
// inputs: 0=query, 1=key, 2=value, 3=attn_mask, 4=W_qkv, 5=b_qkv
// ---------------------------------------------------------------------------
extern "C" void kernel_launch(void* const* d_in, const int* in_sizes, int n_in,
                              void* d_out, int out_size)
{
    const float* query = (const float*)d_in[0];
    const float* mask  = (const float*)d_in[3];
    const float* W     = (const float*)d_in[4];
    const float* bias  = (const float*)d_in[5];
    float* out = (float*)d_out;

    float* qkv;          cudaGetSymbolAddress((void**)&qkv, g_qkv);
    __nv_bfloat16 *ah, *al, *wh, *wl;
    cudaGetSymbolAddress((void**)&ah, g_ah);
    cudaGetSymbolAddress((void**)&al, g_al);
    cudaGetSymbolAddress((void**)&wh, g_wh);
    cudaGetSymbolAddress((void**)&wl, g_wl);

    const int cvt_blocks = (int)((N4_TOTAL + 255) / 256);
    convert_kernel<<<cvt_blocks, 256>>>(query, W);

    cudaFuncSetAttribute(gemm_qkv_mma, cudaFuncAttributeMaxDynamicSharedMemorySize,
                         GEMM_SMEM);
    dim3 ggrid(N_TOT / 128, M_TOT / 128);  // (24, 128)
    gemm_qkv_mma<<<ggrid, 256, GEMM_SMEM>>>(ah, al, wh, wl, bias, qkv);

    attn_kernel<<<M_TOT, 256>>>(qkv, mask, out);
}

// round 4
// speedup vs baseline: 3.0213x; 1.3926x over previous
#include <cuda_runtime.h>
#include <cuda_fp16.h>
#include <cstdint>
#include <math.h>

// ---------------------------------------------------------------------------
// Problem constants
// ---------------------------------------------------------------------------
#define BATCH 4
#define SEQ   4096
#define HID   1024
#define NH    16
#define DH    64
#define M_TOT (BATCH * SEQ)   // 16384
#define N_TOT (3 * HID)       // 3072
#define K_TOT HID             // 1024

// Scratch (device globals: allocation-free rule)
__device__ float  g_qkv[(size_t)M_TOT * N_TOT];  // 192 MB
__device__ __half g_ah[(size_t)M_TOT * K_TOT];   // 32 MB (A in fp16)
__device__ __half g_wh[(size_t)N_TOT * K_TOT];   // 6 MB  (W hi)
__device__ __half g_wl[(size_t)N_TOT * K_TOT];   // 6 MB  (W lo residual)

// ---------------------------------------------------------------------------
// Helpers (sm_80-era PTX only — harness compiles via compute_103, no 'a' features)
// ---------------------------------------------------------------------------
__device__ __forceinline__ uint32_t smem_u32(const void* p) {
    uint32_t a;
    asm("{ .reg .u64 t; cvta.to.shared.u64 t, %1; cvt.u32.u64 %0, t; }"
        : "=r"(a) : "l"(p));
    return a;
}

__device__ __forceinline__ void cp_async16(uint32_t s, const void* g) {
    asm volatile("cp.async.cg.shared.global [%0], [%1], 16;" :: "r"(s), "l"(g) : "memory");
}

__device__ __forceinline__ void ldsm_x4(uint32_t& r0, uint32_t& r1,
                                        uint32_t& r2, uint32_t& r3, uint32_t addr) {
    asm volatile("ldmatrix.sync.aligned.m8n8.x4.shared.b16 {%0,%1,%2,%3}, [%4];"
                 : "=r"(r0), "=r"(r1), "=r"(r2), "=r"(r3) : "r"(addr));
}

__device__ __forceinline__ void mma_fp16(float* c, const uint32_t* a,
                                         uint32_t b0, uint32_t b1) {
    asm volatile(
        "mma.sync.aligned.m16n8k16.row.col.f32.f16.f16.f32 "
        "{%0,%1,%2,%3}, {%4,%5,%6,%7}, {%8,%9}, {%0,%1,%2,%3};"
        : "+f"(c[0]), "+f"(c[1]), "+f"(c[2]), "+f"(c[3])
        : "r"(a[0]), "r"(a[1]), "r"(a[2]), "r"(a[3]), "r"(b0), "r"(b1));
}

// ---------------------------------------------------------------------------
// Conversion: A(fp32) -> fp16, W(fp32) -> fp16 hi + fp16 lo residual
// ---------------------------------------------------------------------------
#define N4_A ((size_t)M_TOT * K_TOT / 4)   // 4194304
#define N4_W ((size_t)N_TOT * K_TOT / 4)   // 786432
#define N4_TOTAL (N4_A + N4_W)

__global__ __launch_bounds__(256) void convert_kernel(
    const float* __restrict__ A, const float* __restrict__ W)
{
    size_t idx = (size_t)blockIdx.x * blockDim.x + threadIdx.x;
    if (idx >= N4_TOTAL) return;

    if (idx < N4_A) {
        float4 v = ((const float4*)A)[idx];
        __half h[4] = { __float2half_rn(v.x), __float2half_rn(v.y),
                        __float2half_rn(v.z), __float2half_rn(v.w) };
        *(uint2*)(g_ah + idx * 4) = *(uint2*)h;
    } else {
        size_t j = idx - N4_A;
        float4 v = ((const float4*)W)[j];
        float f[4] = {v.x, v.y, v.z, v.w};
        __half h[4], l[4];
#pragma unroll
        for (int i = 0; i < 4; i++) {
            h[i] = __float2half_rn(f[i]);
            l[i] = __float2half_rn(f[i] - __half2float(h[i]));
        }
        *(uint2*)(g_wh + j * 4) = *(uint2*)h;
        *(uint2*)(g_wl + j * 4) = *(uint2*)l;
    }
}

// ---------------------------------------------------------------------------
// GEMM via mma.sync fp16x2: C[m,n] = sum_k A[m,k]*(Wh[n,k]+Wl[n,k]) + bias[n]
// CTA tile 128x128, BK=32, 8 warps (warp tile 64x32), 4-stage single-sync
// cp.async pipeline. Smem rows padded to 80B (conflict-free ldmatrix,
// 16B-aligned cp.async).
// ---------------------------------------------------------------------------
#define BK      32
#define KITERS  (K_TOT / BK)     // 32
#define STAGES  4
#define ROWB    80               // 64B data + 16B pad
#define TILEB   (128 * ROWB)     // 10240
#define STAGEB  (3 * TILEB)      // 30720 (Ah, Wh, Wl)
#define GEMM_SMEM (STAGES * STAGEB)  // 122880

__global__ void __launch_bounds__(256, 1) gemm_qkv_mma(
    const __half* __restrict__ Ah, const __half* __restrict__ Wh,
    const __half* __restrict__ Wl,
    const float* __restrict__ bias, float* __restrict__ C)
{
    extern __shared__ char smem[];
    const uint32_t sb = smem_u32(smem);
    const int t    = threadIdx.x;
    const int wid  = t >> 5;
    const int lane = t & 31;
    const int m0 = blockIdx.y * 128;
    const int n0 = blockIdx.x * 128;
    const int wm = (wid & 1) * 64;
    const int wn = (wid >> 1) * 32;

    // cp.async mapping: 6 x 16B chunks per thread per stage
    // i: tile = i>>1 (0=Ah, 1=Wh, 2=Wl), row halves via i&1
    const char* gptr[6];
    uint32_t    soff[6];
#pragma unroll
    for (int i = 0; i < 6; i++) {
        const int tile = i >> 1;
        const int row  = (i & 1) * 64 + (t >> 2);   // 0..127
        const int c    = t & 3;                     // 16B chunk in 64B row
        const __half* base = (tile == 0) ? Ah : (tile == 1) ? Wh : Wl;
        const int grow = ((tile == 0) ? m0 : n0) + row;
        gptr[i] = (const char*)(base + (size_t)grow * K_TOT) + c * 16;
        soff[i] = (uint32_t)(tile * TILEB + row * ROWB + c * 16);
    }

    auto load_stage = [&](int s) {
        const uint32_t dst = sb + (s % STAGES) * STAGEB;
        const int koff = s * (BK * 2);  // 64 bytes per k-stage
#pragma unroll
        for (int i = 0; i < 6; i++)
            cp_async16(dst + soff[i], gptr[i] + koff);
    };

    float acc[4][4][4];
#pragma unroll
    for (int mt = 0; mt < 4; mt++)
#pragma unroll
        for (int nt = 0; nt < 4; nt++)
#pragma unroll
            for (int q = 0; q < 4; q++) acc[mt][nt][q] = 0.0f;

    // Prologue: fill STAGES-1 stages
#pragma unroll
    for (int s = 0; s < STAGES - 1; s++) {
        load_stage(s);
        asm volatile("cp.async.commit_group;" ::: "memory");
    }

    const int lrow  = lane & 15;
    const int lkoff = (lane >> 4) * 16;  // byte offset: 8 fp16

    for (int kit = 0; kit < KITERS; kit++) {
        asm volatile("cp.async.wait_group %0;" :: "n"(STAGES - 2) : "memory");
        __syncthreads();

        // Issue next stage's loads first (into the slot vacated at kit-1)
        if (kit + STAGES - 1 < KITERS) load_stage(kit + STAGES - 1);
        asm volatile("cp.async.commit_group;" ::: "memory");

        const uint32_t bufb = sb + (kit % STAGES) * STAGEB;
        const uint32_t aH = bufb;
        const uint32_t wH = bufb + TILEB;
        const uint32_t wL = bufb + 2 * TILEB;

#pragma unroll
        for (int ks = 0; ks < 2; ks++) {
            const uint32_t kb = (uint32_t)(ks * 32 + lkoff);

            uint32_t af[4][4];
#pragma unroll
            for (int mt = 0; mt < 4; mt++) {
                const uint32_t ro = (uint32_t)((wm + mt * 16 + lrow) * ROWB) + kb;
                ldsm_x4(af[mt][0], af[mt][1], af[mt][2], af[mt][3], aH + ro);
            }

            uint32_t bh0[4], bh1[4], bl0[4], bl1[4];
#pragma unroll
            for (int np = 0; np < 2; np++) {
                const uint32_t ro = (uint32_t)((wn + np * 16 + lrow) * ROWB) + kb;
                uint32_t r0, r1, r2, r3;
                ldsm_x4(r0, r1, r2, r3, wH + ro);
                bh0[np * 2] = r0; bh1[np * 2] = r2;
                bh0[np * 2 + 1] = r1; bh1[np * 2 + 1] = r3;
                ldsm_x4(r0, r1, r2, r3, wL + ro);
                bl0[np * 2] = r0; bl1[np * 2] = r2;
                bl0[np * 2 + 1] = r1; bl1[np * 2 + 1] = r3;
            }

#pragma unroll
            for (int mt = 0; mt < 4; mt++) {
#pragma unroll
                for (int nt = 0; nt < 4; nt++) {
                    mma_fp16(acc[mt][nt], af[mt], bh0[nt], bh1[nt]);  // A*Wh
                    mma_fp16(acc[mt][nt], af[mt], bl0[nt], bl1[nt]);  // A*Wl
                }
            }
        }
    }

    // Epilogue: bias add + store
#pragma unroll
    for (int mt = 0; mt < 4; mt++) {
        const int r = m0 + wm + mt * 16 + (lane >> 2);
#pragma unroll
        for (int nt = 0; nt < 4; nt++) {
            const int cc = n0 + wn + nt * 8 + (lane & 3) * 2;
            const float bx = __ldg(bias + cc);
            const float by = __ldg(bias + cc + 1);
            float2 v0, v1;
            v0.x = acc[mt][nt][0] + bx; v0.y = acc[mt][nt][1] + by;
            v1.x = acc[mt][nt][2] + bx; v1.y = acc[mt][nt][3] + by;
            *(float2*)(C + (size_t)r * N_TOT + cc)       = v0;
            *(float2*)(C + (size_t)(r + 8) * N_TOT + cc) = v1;
        }
    }
}

// ---------------------------------------------------------------------------
// Attention: one block per (b,s) position. Bank-conflict-free smem layouts.
// ---------------------------------------------------------------------------
__global__ __launch_bounds__(256) void attn_kernel(
    const float* __restrict__ qkv, const float* __restrict__ mask,
    float* __restrict__ out)
{
    __shared__ float sq[NH][DH + 1];
    __shared__ float sk[NH][DH + 1];
    __shared__ float sv[HID];
    __shared__ float sw[NH][17];
    __shared__ float srmax[NH];
    __shared__ float srsuminv[NH];

    const int p = blockIdx.x;
    const int t = threadIdx.x;

    {
        const float4* src = (const float4*)(qkv + (size_t)p * N_TOT);
        const int hh = t >> 4;
        const int dd = (t & 15) * 4;
        float4 a = src[t];
        sq[hh][dd + 0] = a.x; sq[hh][dd + 1] = a.y;
        sq[hh][dd + 2] = a.z; sq[hh][dd + 3] = a.w;
        float4 b = src[256 + t];
        sk[hh][dd + 0] = b.x; sk[hh][dd + 1] = b.y;
        sk[hh][dd + 2] = b.z; sk[hh][dd + 3] = b.w;
        ((float4*)sv)[t] = src[512 + t];
    }
    __syncthreads();

    const int h = t >> 4;
    const int g = t & 15;

    {
        float s = 0.0f;
#pragma unroll
        for (int d = 0; d < DH; d++) s += sq[h][d] * sk[g][d];
        s = s * 0.125f + __ldg(mask + (size_t)p * (NH * NH) + t);
        sw[h][g] = s;
    }
    __syncthreads();

    if (t < NH) {
        float mx = -INFINITY;
#pragma unroll
        for (int j = 0; j < NH; j++) mx = fmaxf(mx, sw[t][j]);
        float sum = 0.0f;
#pragma unroll
        for (int j = 0; j < NH; j++) sum += __expf(sw[t][j] - mx);
        srmax[t] = mx;
        srsuminv[t] = 1.0f / sum;
    }
    __syncthreads();

    const float w = __expf(sw[h][g] - srmax[h]) * srsuminv[h];
    __syncthreads();
    sw[h][g] = w;
    __syncthreads();

    const int d0 = (t & 15) * 4;
    float4 acc = make_float4(0.f, 0.f, 0.f, 0.f);
#pragma unroll
    for (int gg = 0; gg < NH; gg++) {
        const float wv = sw[h][gg];
        const float4 v4 = *(const float4*)(sv + gg * DH + d0);
        acc.x += wv * v4.x; acc.y += wv * v4.y;
        acc.z += wv * v4.z; acc.w += wv * v4.w;
    }
    *(float4*)(out + (size_t)p * HID + h * DH + d0) = acc;
}

// ---------------------------------------------------------------------------
// Launch — inputs: 0=query, 1=key, 2=value, 3=attn_mask, 4=W_qkv, 5=b_qkv
// ---------------------------------------------------------------------------
extern "C" void kernel_launch(void* const* d_in, const int* in_sizes, int n_in,
                              void* d_out, int out_size)
{
    const float* query = (const float*)d_in[0];
    const float* mask  = (const float*)d_in[3];
    const float* W     = (const float*)d_in[4];
    const float* bias  = (const float*)d_in[5];
    float* out = (float*)d_out;

    float* qkv; cudaGetSymbolAddress((void**)&qkv, g_qkv);
    __half *ah, *wh, *wl;
    cudaGetSymbolAddress((void**)&ah, g_ah);
    cudaGetSymbolAddress((void**)&wh, g_wh);
    cudaGetSymbolAddress((void**)&wl, g_wl);

    const int cvt_blocks = (int)((N4_TOTAL + 255) / 256);
    convert_kernel<<<cvt_blocks, 256>>>(query, W);

    cudaFuncSetAttribute(gemm_qkv_mma, cudaFuncAttributeMaxDynamicSharedMemorySize,
                         GEMM_SMEM);
    dim3 ggrid(N_TOT / 128, M_TOT / 128);  // (24, 128)
    gemm_qkv_mma<<<ggrid, 256, GEMM_SMEM>>>(ah, wh, wl, bias, qkv);

    attn_kernel<<<M_TOT, 256>>>(qkv, mask, out);
}

// round 5
// speedup vs baseline: 3.0851x; 1.0211x over previous
#include <cuda_runtime.h>
#include <cuda_fp16.h>
#include <cstdint>
#include <math.h>

// ---------------------------------------------------------------------------
// Problem constants
// ---------------------------------------------------------------------------
#define BATCH 4
#define SEQ   4096
#define HID   1024
#define NH    16
#define DH    64
#define M_TOT (BATCH * SEQ)   // 16384
#define N_TOT (3 * HID)       // 3072
#define K_TOT HID             // 1024

// Scratch (device globals: allocation-free rule)
__device__ __half g_qkv[(size_t)M_TOT * N_TOT];  // 96 MB (fp16 qkv)
__device__ __half g_ah[(size_t)M_TOT * K_TOT];   // 32 MB (A fp16)
__device__ __half g_wh[(size_t)N_TOT * K_TOT];   // 6 MB  (W hi)
__device__ __half g_wl[(size_t)N_TOT * K_TOT];   // 6 MB  (W lo residual)

// ---------------------------------------------------------------------------
// Helpers (sm_80-era PTX only — harness compiles via compute_103, no 'a' features)
// ---------------------------------------------------------------------------
__device__ __forceinline__ uint32_t smem_u32(const void* p) {
    uint32_t a;
    asm("{ .reg .u64 t; cvta.to.shared.u64 t, %1; cvt.u32.u64 %0, t; }"
        : "=r"(a) : "l"(p));
    return a;
}

__device__ __forceinline__ void cp_async16(uint32_t s, const void* g) {
    asm volatile("cp.async.cg.shared.global [%0], [%1], 16;" :: "r"(s), "l"(g) : "memory");
}

__device__ __forceinline__ void ldsm_x4(uint32_t& r0, uint32_t& r1,
                                        uint32_t& r2, uint32_t& r3, uint32_t addr) {
    asm volatile("ldmatrix.sync.aligned.m8n8.x4.shared.b16 {%0,%1,%2,%3}, [%4];"
                 : "=r"(r0), "=r"(r1), "=r"(r2), "=r"(r3) : "r"(addr));
}

__device__ __forceinline__ void mma_fp16(float* c, const uint32_t* a,
                                         uint32_t b0, uint32_t b1) {
    asm volatile(
        "mma.sync.aligned.m16n8k16.row.col.f32.f16.f16.f32 "
        "{%0,%1,%2,%3}, {%4,%5,%6,%7}, {%8,%9}, {%0,%1,%2,%3};"
        : "+f"(c[0]), "+f"(c[1]), "+f"(c[2]), "+f"(c[3])
        : "r"(a[0]), "r"(a[1]), "r"(a[2]), "r"(a[3]), "r"(b0), "r"(b1));
}

// ---------------------------------------------------------------------------
// Conversion: A(fp32) -> fp16, W(fp32) -> fp16 hi + fp16 lo residual
// ---------------------------------------------------------------------------
#define N4_A ((size_t)M_TOT * K_TOT / 4)   // 4194304
#define N4_W ((size_t)N_TOT * K_TOT / 4)   // 786432
#define N4_TOTAL (N4_A + N4_W)

__global__ __launch_bounds__(256) void convert_kernel(
    const float* __restrict__ A, const float* __restrict__ W)
{
    size_t idx = (size_t)blockIdx.x * blockDim.x + threadIdx.x;
    if (idx >= N4_TOTAL) return;

    if (idx < N4_A) {
        float4 v = ((const float4*)A)[idx];
        __half h[4] = { __float2half_rn(v.x), __float2half_rn(v.y),
                        __float2half_rn(v.z), __float2half_rn(v.w) };
        *(uint2*)(g_ah + idx * 4) = *(uint2*)h;
    } else {
        size_t j = idx - N4_A;
        float4 v = ((const float4*)W)[j];
        float f[4] = {v.x, v.y, v.z, v.w};
        __half h[4], l[4];
#pragma unroll
        for (int i = 0; i < 4; i++) {
            h[i] = __float2half_rn(f[i]);
            l[i] = __float2half_rn(f[i] - __half2float(h[i]));
        }
        *(uint2*)(g_wh + j * 4) = *(uint2*)h;
        *(uint2*)(g_wl + j * 4) = *(uint2*)l;
    }
}

// ---------------------------------------------------------------------------
// GEMM via mma.sync fp16x2: qkv[m,n] = sum_k A[m,k]*(Wh[n,k]+Wl[n,k]) + bias[n]
// CTA 128x128, BK=32, 8 warps (warp tile 64x32), 4-stage single-sync cp.async.
// MMA issue order: all 16 independent hi-pass MMAs, then all 16 lo-pass MMAs
// (acc RAW distance = 16 issues -> HMMA latency hidden).
// Output stored as fp16.
// ---------------------------------------------------------------------------
#define BK      32
#define KITERS  (K_TOT / BK)     // 32
#define STAGES  4
#define ROWB    80               // 64B data + 16B pad
#define TILEB   (128 * ROWB)     // 10240
#define STAGEB  (3 * TILEB)      // 30720 (Ah, Wh, Wl)
#define GEMM_SMEM (STAGES * STAGEB)  // 122880

__global__ void __launch_bounds__(256, 1) gemm_qkv_mma(
    const __half* __restrict__ Ah, const __half* __restrict__ Wh,
    const __half* __restrict__ Wl,
    const float* __restrict__ bias, __half* __restrict__ C)
{
    extern __shared__ char smem[];
    const uint32_t sb = smem_u32(smem);
    const int t    = threadIdx.x;
    const int wid  = t >> 5;
    const int lane = t & 31;
    const int m0 = blockIdx.y * 128;
    const int n0 = blockIdx.x * 128;
    const int wm = (wid & 1) * 64;
    const int wn = (wid >> 1) * 32;

    // cp.async mapping: 6 x 16B chunks per thread per stage
    const char* gptr[6];
    uint32_t    soff[6];
#pragma unroll
    for (int i = 0; i < 6; i++) {
        const int tile = i >> 1;
        const int row  = (i & 1) * 64 + (t >> 2);
        const int c    = t & 3;
        const __half* base = (tile == 0) ? Ah : (tile == 1) ? Wh : Wl;
        const int grow = ((tile == 0) ? m0 : n0) + row;
        gptr[i] = (const char*)(base + (size_t)grow * K_TOT) + c * 16;
        soff[i] = (uint32_t)(tile * TILEB + row * ROWB + c * 16);
    }

    auto load_stage = [&](int s) {
        const uint32_t dst = sb + (s % STAGES) * STAGEB;
        const int koff = s * (BK * 2);
#pragma unroll
        for (int i = 0; i < 6; i++)
            cp_async16(dst + soff[i], gptr[i] + koff);
    };

    float acc[4][4][4];
#pragma unroll
    for (int mt = 0; mt < 4; mt++)
#pragma unroll
        for (int nt = 0; nt < 4; nt++)
#pragma unroll
            for (int q = 0; q < 4; q++) acc[mt][nt][q] = 0.0f;

#pragma unroll
    for (int s = 0; s < STAGES - 1; s++) {
        load_stage(s);
        asm volatile("cp.async.commit_group;" ::: "memory");
    }

    const int lrow  = lane & 15;
    const int lkoff = (lane >> 4) * 16;

    for (int kit = 0; kit < KITERS; kit++) {
        asm volatile("cp.async.wait_group %0;" :: "n"(STAGES - 2) : "memory");
        __syncthreads();

        if (kit + STAGES - 1 < KITERS) load_stage(kit + STAGES - 1);
        asm volatile("cp.async.commit_group;" ::: "memory");

        const uint32_t bufb = sb + (kit % STAGES) * STAGEB;
        const uint32_t aH = bufb;
        const uint32_t wH = bufb + TILEB;
        const uint32_t wL = bufb + 2 * TILEB;

#pragma unroll
        for (int ks = 0; ks < 2; ks++) {
            const uint32_t kb = (uint32_t)(ks * 32 + lkoff);

            uint32_t af[4][4];
#pragma unroll
            for (int mt = 0; mt < 4; mt++) {
                const uint32_t ro = (uint32_t)((wm + mt * 16 + lrow) * ROWB) + kb;
                ldsm_x4(af[mt][0], af[mt][1], af[mt][2], af[mt][3], aH + ro);
            }

            uint32_t bh0[4], bh1[4], bl0[4], bl1[4];
#pragma unroll
            for (int np = 0; np < 2; np++) {
                const uint32_t ro = (uint32_t)((wn + np * 16 + lrow) * ROWB) + kb;
                uint32_t r0, r1, r2, r3;
                ldsm_x4(r0, r1, r2, r3, wH + ro);
                bh0[np * 2] = r0; bh1[np * 2] = r2;
                bh0[np * 2 + 1] = r1; bh1[np * 2 + 1] = r3;
                ldsm_x4(r0, r1, r2, r3, wL + ro);
                bl0[np * 2] = r0; bl1[np * 2] = r2;
                bl0[np * 2 + 1] = r1; bl1[np * 2 + 1] = r3;
            }

            // Pass 1: 16 independent MMAs (A*Wh)
#pragma unroll
            for (int mt = 0; mt < 4; mt++)
#pragma unroll
                for (int nt = 0; nt < 4; nt++)
                    mma_fp16(acc[mt][nt], af[mt], bh0[nt], bh1[nt]);
            // Pass 2: 16 independent MMAs (A*Wl), RAW distance = 16 issues
#pragma unroll
            for (int mt = 0; mt < 4; mt++)
#pragma unroll
                for (int nt = 0; nt < 4; nt++)
                    mma_fp16(acc[mt][nt], af[mt], bl0[nt], bl1[nt]);
        }
    }

    // Epilogue: bias add + fp16 store
#pragma unroll
    for (int mt = 0; mt < 4; mt++) {
        const int r = m0 + wm + mt * 16 + (lane >> 2);
#pragma unroll
        for (int nt = 0; nt < 4; nt++) {
            const int cc = n0 + wn + nt * 8 + (lane & 3) * 2;
            const float bx = __ldg(bias + cc);
            const float by = __ldg(bias + cc + 1);
            __half2 h0, h1;
            h0.x = __float2half_rn(acc[mt][nt][0] + bx);
            h0.y = __float2half_rn(acc[mt][nt][1] + by);
            h1.x = __float2half_rn(acc[mt][nt][2] + bx);
            h1.y = __float2half_rn(acc[mt][nt][3] + by);
            *(__half2*)(C + (size_t)r * N_TOT + cc)       = h0;
            *(__half2*)(C + (size_t)(r + 8) * N_TOT + cc) = h1;
        }
    }
}

// ---------------------------------------------------------------------------
// Attention: one block per (b,s) position. fp16 qkv input, fp32 compute.
// ---------------------------------------------------------------------------
__global__ __launch_bounds__(256) void attn_kernel(
    const __half* __restrict__ qkv, const float* __restrict__ mask,
    float* __restrict__ out)
{
    __shared__ float sq[NH][DH + 1];
    __shared__ float sk[NH][DH + 1];
    __shared__ float sv[HID];
    __shared__ float sw[NH][17];
    __shared__ float srmax[NH];
    __shared__ float srsuminv[NH];

    const int p = blockIdx.x;
    const int t = threadIdx.x;

    // Load 3072 halfs = 384 uint4 (8 halfs each); 256 threads -> 1.5 per thread
    {
        const uint4* src = (const uint4*)(qkv + (size_t)p * N_TOT);
#pragma unroll
        for (int i = t; i < 384; i += 256) {
            uint4 raw = src[i];
            const __half2* hp = (const __half2*)&raw;
            float f[8];
#pragma unroll
            for (int j = 0; j < 4; j++) {
                float2 fv = __half22float2(hp[j]);
                f[j * 2] = fv.x; f[j * 2 + 1] = fv.y;
            }
            const int base = i * 8;         // element in 0..3071
            if (base < HID) {
                const int hh = base >> 6, dd = base & 63;
#pragma unroll
                for (int j = 0; j < 8; j++) sq[hh][dd + j] = f[j];
            } else if (base < 2 * HID) {
                const int e = base - HID;
                const int hh = e >> 6, dd = e & 63;
#pragma unroll
                for (int j = 0; j < 8; j++) sk[hh][dd + j] = f[j];
            } else {
                const int e = base - 2 * HID;
#pragma unroll
                for (int j = 0; j < 8; j++) sv[e + j] = f[j];
            }
        }
    }
    __syncthreads();

    const int h = t >> 4;
    const int g = t & 15;

    {
        float s = 0.0f;
#pragma unroll
        for (int d = 0; d < DH; d++) s += sq[h][d] * sk[g][d];
        s = s * 0.125f + __ldg(mask + (size_t)p * (NH * NH) + t);
        sw[h][g] = s;
    }
    __syncthreads();

    if (t < NH) {
        float mx = -INFINITY;
#pragma unroll
        for (int j = 0; j < NH; j++) mx = fmaxf(mx, sw[t][j]);
        float sum = 0.0f;
#pragma unroll
        for (int j = 0; j < NH; j++) sum += __expf(sw[t][j] - mx);
        srmax[t] = mx;
        srsuminv[t] = 1.0f / sum;
    }
    __syncthreads();

    const float w = __expf(sw[h][g] - srmax[h]) * srsuminv[h];
    __syncthreads();
    sw[h][g] = w;
    __syncthreads();

    const int d0 = (t & 15) * 4;
    float4 acc = make_float4(0.f, 0.f, 0.f, 0.f);
#pragma unroll
    for (int gg = 0; gg < NH; gg++) {
        const float wv = sw[h][gg];
        const float4 v4 = *(const float4*)(sv + gg * DH + d0);
        acc.x += wv * v4.x; acc.y += wv * v4.y;
        acc.z += wv * v4.z; acc.w += wv * v4.w;
    }
    *(float4*)(out + (size_t)p * HID + h * DH + d0) = acc;
}

// ---------------------------------------------------------------------------
// Launch — inputs: 0=query, 1=key, 2=value, 3=attn_mask, 4=W_qkv, 5=b_qkv
// ---------------------------------------------------------------------------
extern "C" void kernel_launch(void* const* d_in, const int* in_sizes, int n_in,
                              void* d_out, int out_size)
{
    const float* query = (const float*)d_in[0];
    const float* mask  = (const float*)d_in[3];
    const float* W     = (const float*)d_in[4];
    const float* bias  = (const float*)d_in[5];
    float* out = (float*)d_out;

    __half *qkv, *ah, *wh, *wl;
    cudaGetSymbolAddress((void**)&qkv, g_qkv);
    cudaGetSymbolAddress((void**)&ah, g_ah);
    cudaGetSymbolAddress((void**)&wh, g_wh);
    cudaGetSymbolAddress((void**)&wl, g_wl);

    const int cvt_blocks = (int)((N4_TOTAL + 255) / 256);
    convert_kernel<<<cvt_blocks, 256>>>(query, W);

    cudaFuncSetAttribute(gemm_qkv_mma, cudaFuncAttributeMaxDynamicSharedMemorySize,
                         GEMM_SMEM);
    dim3 ggrid(N_TOT / 128, M_TOT / 128);  // (24, 128)
    gemm_qkv_mma<<<ggrid, 256, GEMM_SMEM>>>(ah, wh, wl, bias, qkv);

    attn_kernel<<<M_TOT, 256>>>(qkv, mask, out);
}

// round 7
// speedup vs baseline: 3.7767x; 1.2242x over previous
#include <cuda_runtime.h>
#include <cuda_fp16.h>
#include <cstdint>
#include <math.h>

// ---------------------------------------------------------------------------
// Problem constants
// ---------------------------------------------------------------------------
#define BATCH 4
#define SEQ   4096
#define HID   1024
#define NH    16
#define DH    64
#define M_TOT (BATCH * SEQ)   // 16384
#define N_TOT (3 * HID)       // 3072
#define K_TOT HID             // 1024

// Scratch (device globals: allocation-free rule)
__device__ __half g_qkv[(size_t)M_TOT * N_TOT];  // 96 MB
__device__ __half g_ah[(size_t)M_TOT * K_TOT];   // 32 MB
__device__ __half g_wh[(size_t)N_TOT * K_TOT];   // 6 MB
__device__ __half g_wl[(size_t)N_TOT * K_TOT];   // 6 MB

// ---------------------------------------------------------------------------
// Helpers (sm_80-era PTX only)
// ---------------------------------------------------------------------------
__device__ __forceinline__ uint32_t smem_u32(const void* p) {
    uint32_t a;
    asm("{ .reg .u64 t; cvta.to.shared.u64 t, %1; cvt.u32.u64 %0, t; }"
        : "=r"(a) : "l"(p));
    return a;
}

__device__ __forceinline__ void cp_async16(uint32_t s, const void* g) {
    asm volatile("cp.async.cg.shared.global [%0], [%1], 16;" :: "r"(s), "l"(g) : "memory");
}

__device__ __forceinline__ void ldsm_x4(uint32_t& r0, uint32_t& r1,
                                        uint32_t& r2, uint32_t& r3, uint32_t addr) {
    asm volatile("ldmatrix.sync.aligned.m8n8.x4.shared.b16 {%0,%1,%2,%3}, [%4];"
                 : "=r"(r0), "=r"(r1), "=r"(r2), "=r"(r3) : "r"(addr));
}

__device__ __forceinline__ void mma_fp16(float* c, const uint32_t* a,
                                         uint32_t b0, uint32_t b1) {
    asm volatile(
        "mma.sync.aligned.m16n8k16.row.col.f32.f16.f16.f32 "
        "{%0,%1,%2,%3}, {%4,%5,%6,%7}, {%8,%9}, {%0,%1,%2,%3};"
        : "+f"(c[0]), "+f"(c[1]), "+f"(c[2]), "+f"(c[3])
        : "r"(a[0]), "r"(a[1]), "r"(a[2]), "r"(a[3]), "r"(b0), "r"(b1));
}

// ---------------------------------------------------------------------------
// Conversion: A(fp32) -> fp16, W(fp32) -> fp16 hi + fp16 lo residual
// ---------------------------------------------------------------------------
#define N4_A ((size_t)M_TOT * K_TOT / 4)
#define N4_W ((size_t)N_TOT * K_TOT / 4)
#define N4_TOTAL (N4_A + N4_W)

__global__ __launch_bounds__(256) void convert_kernel(
    const float* __restrict__ A, const float* __restrict__ W)
{
    size_t idx = (size_t)blockIdx.x * blockDim.x + threadIdx.x;
    if (idx >= N4_TOTAL) return;

    if (idx < N4_A) {
        float4 v = ((const float4*)A)[idx];
        __half h[4] = { __float2half_rn(v.x), __float2half_rn(v.y),
                        __float2half_rn(v.z), __float2half_rn(v.w) };
        *(uint2*)(g_ah + idx * 4) = *(uint2*)h;
    } else {
        size_t j = idx - N4_A;
        float4 v = ((const float4*)W)[j];
        float f[4] = {v.x, v.y, v.z, v.w};
        __half h[4], l[4];
#pragma unroll
        for (int i = 0; i < 4; i++) {
            h[i] = __float2half_rn(f[i]);
            l[i] = __float2half_rn(f[i] - __half2float(h[i]));
        }
        *(uint2*)(g_wh + j * 4) = *(uint2*)h;
        *(uint2*)(g_wl + j * 4) = *(uint2*)l;
    }
}

// ---------------------------------------------------------------------------
// GEMM fp16x2: CTA 128x128, BK=32, 3-stage cp.async, 2 CTAs/SM.
// ---------------------------------------------------------------------------
#define BK      32
#define KITERS  (K_TOT / BK)     // 32
#define STAGES  3
#define ROWB    80
#define TILEB   (128 * ROWB)     // 10240
#define STAGEB  (3 * TILEB)      // 30720
#define GEMM_SMEM (STAGES * STAGEB)  // 92160 -> 2 CTAs/SM

__global__ void __launch_bounds__(256, 2) gemm_qkv_mma(
    const __half* __restrict__ Ah, const __half* __restrict__ Wh,
    const __half* __restrict__ Wl,
    const float* __restrict__ bias, __half* __restrict__ C)
{
    extern __shared__ char smem[];
    const uint32_t sb = smem_u32(smem);
    const int t    = threadIdx.x;
    const int wid  = t >> 5;
    const int lane = t & 31;
    const int m0 = blockIdx.y * 128;
    const int n0 = blockIdx.x * 128;
    const int wm = (wid & 1) * 64;
    const int wn = (wid >> 1) * 32;

    const char* gptr[6];
    uint32_t    soff[6];
#pragma unroll
    for (int i = 0; i < 6; i++) {
        const int tile = i >> 1;
        const int row  = (i & 1) * 64 + (t >> 2);
        const int c    = t & 3;
        const __half* base = (tile == 0) ? Ah : (tile == 1) ? Wh : Wl;
        const int grow = ((tile == 0) ? m0 : n0) + row;
        gptr[i] = (const char*)(base + (size_t)grow * K_TOT) + c * 16;
        soff[i] = (uint32_t)(tile * TILEB + row * ROWB + c * 16);
    }

    auto load_stage = [&](int s) {
        const uint32_t dst = sb + (s % STAGES) * STAGEB;
        const int koff = s * (BK * 2);
#pragma unroll
        for (int i = 0; i < 6; i++)
            cp_async16(dst + soff[i], gptr[i] + koff);
    };

    float acc[4][4][4];
#pragma unroll
    for (int mt = 0; mt < 4; mt++)
#pragma unroll
        for (int nt = 0; nt < 4; nt++)
#pragma unroll
            for (int q = 0; q < 4; q++) acc[mt][nt][q] = 0.0f;

#pragma unroll
    for (int s = 0; s < STAGES - 1; s++) {
        load_stage(s);
        asm volatile("cp.async.commit_group;" ::: "memory");
    }

    const int lrow  = lane & 15;
    const int lkoff = (lane >> 4) * 16;

    for (int kit = 0; kit < KITERS; kit++) {
        asm volatile("cp.async.wait_group %0;" :: "n"(STAGES - 2) : "memory");
        __syncthreads();

        if (kit + STAGES - 1 < KITERS) load_stage(kit + STAGES - 1);
        asm volatile("cp.async.commit_group;" ::: "memory");

        const uint32_t bufb = sb + (kit % STAGES) * STAGEB;
        const uint32_t aH = bufb;
        const uint32_t wH = bufb + TILEB;
        const uint32_t wL = bufb + 2 * TILEB;

#pragma unroll
        for (int ks = 0; ks < 2; ks++) {
            const uint32_t kb = (uint32_t)(ks * 32 + lkoff);

            uint32_t af[4][4];
#pragma unroll
            for (int mt = 0; mt < 4; mt++) {
                const uint32_t ro = (uint32_t)((wm + mt * 16 + lrow) * ROWB) + kb;
                ldsm_x4(af[mt][0], af[mt][1], af[mt][2], af[mt][3], aH + ro);
            }

            uint32_t bh0[4], bh1[4], bl0[4], bl1[4];
#pragma unroll
            for (int np = 0; np < 2; np++) {
                const uint32_t ro = (uint32_t)((wn + np * 16 + lrow) * ROWB) + kb;
                uint32_t r0, r1, r2, r3;
                ldsm_x4(r0, r1, r2, r3, wH + ro);
                bh0[np * 2] = r0; bh1[np * 2] = r2;
                bh0[np * 2 + 1] = r1; bh1[np * 2 + 1] = r3;
                ldsm_x4(r0, r1, r2, r3, wL + ro);
                bl0[np * 2] = r0; bl1[np * 2] = r2;
                bl0[np * 2 + 1] = r1; bl1[np * 2 + 1] = r3;
            }

#pragma unroll
            for (int mt = 0; mt < 4; mt++)
#pragma unroll
                for (int nt = 0; nt < 4; nt++)
                    mma_fp16(acc[mt][nt], af[mt], bh0[nt], bh1[nt]);
#pragma unroll
            for (int mt = 0; mt < 4; mt++)
#pragma unroll
                for (int nt = 0; nt < 4; nt++)
                    mma_fp16(acc[mt][nt], af[mt], bl0[nt], bl1[nt]);
        }
    }

    // Epilogue: bias add + fp16 store
#pragma unroll
    for (int mt = 0; mt < 4; mt++) {
        const int r = m0 + wm + mt * 16 + (lane >> 2);
#pragma unroll
        for (int nt = 0; nt < 4; nt++) {
            const int cc = n0 + wn + nt * 8 + (lane & 3) * 2;
            const float bx = __ldg(bias + cc);
            const float by = __ldg(bias + cc + 1);
            __half2 h0, h1;
            h0.x = __float2half_rn(acc[mt][nt][0] + bx);
            h0.y = __float2half_rn(acc[mt][nt][1] + by);
            h1.x = __float2half_rn(acc[mt][nt][2] + bx);
            h1.y = __float2half_rn(acc[mt][nt][3] + by);
            *(__half2*)(C + (size_t)r * N_TOT + cc)       = h0;
            *(__half2*)(C + (size_t)(r + 8) * N_TOT + cc) = h1;
        }
    }
}

// ---------------------------------------------------------------------------
// Attention: WARP-per-position. 128-thr blocks = 4 positions. No block syncs.
// Per-warp smem (8000B): q/k/v fp16 [3][16][72] + w fp32 [16][17].
// FIX vs R6: load loop covers all 384 uint4 (3072 halfs), not 96.
// ---------------------------------------------------------------------------
__global__ __launch_bounds__(128) void attn_kernel(
    const __half* __restrict__ qkv, const float* __restrict__ mask,
    float* __restrict__ out)
{
    __shared__ __align__(16) unsigned char sm[4][8000];

    const int wid  = threadIdx.x >> 5;
    const int lane = threadIdx.x & 31;
    const int p = blockIdx.x * 4 + wid;

    __half* sqkv = (__half*)sm[wid];                 // arr*1152 + h*72 + d
    float*  sw   = (float*)(sm[wid] + 6912);         // [16][17]

    // Load 3072 halfs = 384 uint4; 12 per lane
    {
        const uint4* src = (const uint4*)(qkv + (size_t)p * N_TOT);
#pragma unroll
        for (int i = lane; i < 384; i += 32) {
            uint4 raw = src[i];
            const int e = i * 8;
            const int arr = e >> 10;          // 0=q, 1=k, 2=v
            const int r   = e & 1023;
            *(uint4*)(sqkv + arr * 1152 + (r >> 6) * 72 + (r & 63)) = raw;
        }
    }
    __syncwarp();

    const int h  = lane >> 1;
    const int gh = lane & 1;

    // ---- QK: 8 dot products of length 64 ----
    float s[8];
#pragma unroll
    for (int gi = 0; gi < 8; gi++) s[gi] = 0.0f;

    const __half* qrow = sqkv + h * 72;
#pragma unroll
    for (int d8 = 0; d8 < 8; d8++) {
        uint4 qraw = *(const uint4*)(qrow + d8 * 8);
        const __half2* qh2 = (const __half2*)&qraw;
        float qf[8];
#pragma unroll
        for (int j = 0; j < 4; j++) {
            float2 f = __half22float2(qh2[j]);
            qf[2 * j] = f.x; qf[2 * j + 1] = f.y;
        }
#pragma unroll
        for (int gi = 0; gi < 8; gi++) {
            const __half* krow = sqkv + 1152 + (gh * 8 + gi) * 72;
            uint4 kraw = *(const uint4*)(krow + d8 * 8);
            const __half2* kh2 = (const __half2*)&kraw;
#pragma unroll
            for (int j = 0; j < 4; j++) {
                float2 f = __half22float2(kh2[j]);
                s[gi] += qf[2 * j] * f.x + qf[2 * j + 1] * f.y;
            }
        }
    }

    // scale + mask
    {
        const float* mrow = mask + (size_t)p * (NH * NH) + h * NH + gh * 8;
        float4 m0 = *(const float4*)mrow;
        float4 m1 = *(const float4*)(mrow + 4);
        const float mf[8] = {m0.x, m0.y, m0.z, m0.w, m1.x, m1.y, m1.z, m1.w};
#pragma unroll
        for (int gi = 0; gi < 8; gi++) s[gi] = s[gi] * 0.125f + mf[gi];
    }

    // ---- softmax across the 16-wide row (2 lanes per row) ----
    float mx = s[0];
#pragma unroll
    for (int gi = 1; gi < 8; gi++) mx = fmaxf(mx, s[gi]);
    mx = fmaxf(mx, __shfl_xor_sync(0xffffffff, mx, 1));

    float e[8], sum = 0.0f;
#pragma unroll
    for (int gi = 0; gi < 8; gi++) { e[gi] = __expf(s[gi] - mx); sum += e[gi]; }
    sum += __shfl_xor_sync(0xffffffff, sum, 1);
    const float inv = 1.0f / sum;

#pragma unroll
    for (int gi = 0; gi < 8; gi++) sw[h * 17 + gh * 8 + gi] = e[gi] * inv;
    __syncwarp();

    // ---- PV: lane computes out[h][gh*32 .. gh*32+31] ----
    float acc[32];
#pragma unroll
    for (int d = 0; d < 32; d++) acc[d] = 0.0f;

#pragma unroll
    for (int g = 0; g < 16; g++) {
        const float wv = sw[h * 17 + g];
        const __half* vrow = sqkv + 2304 + g * 72 + gh * 32;
#pragma unroll
        for (int d8 = 0; d8 < 4; d8++) {
            uint4 vr = *(const uint4*)(vrow + d8 * 8);
            const __half2* vh2 = (const __half2*)&vr;
#pragma unroll
            for (int j = 0; j < 4; j++) {
                float2 f = __half22float2(vh2[j]);
                acc[d8 * 8 + 2 * j]     += wv * f.x;
                acc[d8 * 8 + 2 * j + 1] += wv * f.y;
            }
        }
    }

    float* orow = out + (size_t)p * HID + h * DH + gh * 32;
#pragma unroll
    for (int d4 = 0; d4 < 8; d4++) {
        float4 o;
        o.x = acc[4 * d4]; o.y = acc[4 * d4 + 1];
        o.z = acc[4 * d4 + 2]; o.w = acc[4 * d4 + 3];
        *(float4*)(orow + 4 * d4) = o;
    }
}

// ---------------------------------------------------------------------------
// Launch — inputs: 0=query, 1=key, 2=value, 3=attn_mask, 4=W_qkv, 5=b_qkv
// ---------------------------------------------------------------------------
extern "C" void kernel_launch(void* const* d_in, const int* in_sizes, int n_in,
                              void* d_out, int out_size)
{
    const float* query = (const float*)d_in[0];
    const float* mask  = (const float*)d_in[3];
    const float* W     = (const float*)d_in[4];
    const float* bias  = (const float*)d_in[5];
    float* out = (float*)d_out;

    __half *qkv, *ah, *wh, *wl;
    cudaGetSymbolAddress((void**)&qkv, g_qkv);
    cudaGetSymbolAddress((void**)&ah, g_ah);
    cudaGetSymbolAddress((void**)&wh, g_wh);
    cudaGetSymbolAddress((void**)&wl, g_wl);

    const int cvt_blocks = (int)((N4_TOTAL + 255) / 256);
    convert_kernel<<<cvt_blocks, 256>>>(query, W);

    cudaFuncSetAttribute(gemm_qkv_mma, cudaFuncAttributeMaxDynamicSharedMemorySize,
                         GEMM_SMEM);
    dim3 ggrid(N_TOT / 128, M_TOT / 128);  // (24, 128)
    gemm_qkv_mma<<<ggrid, 256, GEMM_SMEM>>>(ah, wh, wl, bias, qkv);

    attn_kernel<<<M_TOT / 4, 128>>>(qkv, mask, out);
}

// round 8
// speedup vs baseline: 6.2282x; 1.6491x over previous
#include <cuda_runtime.h>
#include <cuda_fp16.h>
#include <cstdint>
#include <math.h>

// ---------------------------------------------------------------------------
// Problem constants
// ---------------------------------------------------------------------------
#define BATCH 4
#define SEQ   4096
#define HID   1024
#define NH    16
#define DH    64
#define M_TOT (BATCH * SEQ)   // 16384
#define N_TOT (3 * HID)       // 3072
#define K_TOT HID             // 1024

// Scratch (device globals: allocation-free rule)
__device__ __half g_qkv[(size_t)M_TOT * N_TOT];  // 96 MB
__device__ __half g_ah[(size_t)M_TOT * K_TOT];   // 32 MB
__device__ __half g_wh[(size_t)N_TOT * K_TOT];   // 6 MB

// ---------------------------------------------------------------------------
// Helpers (sm_80-era PTX only)
// ---------------------------------------------------------------------------
__device__ __forceinline__ uint32_t smem_u32(const void* p) {
    uint32_t a;
    asm("{ .reg .u64 t; cvta.to.shared.u64 t, %1; cvt.u32.u64 %0, t; }"
        : "=r"(a) : "l"(p));
    return a;
}

__device__ __forceinline__ void cp_async16(uint32_t s, const void* g) {
    asm volatile("cp.async.cg.shared.global [%0], [%1], 16;" :: "r"(s), "l"(g) : "memory");
}

__device__ __forceinline__ void ldsm_x4(uint32_t& r0, uint32_t& r1,
                                        uint32_t& r2, uint32_t& r3, uint32_t addr) {
    asm volatile("ldmatrix.sync.aligned.m8n8.x4.shared.b16 {%0,%1,%2,%3}, [%4];"
                 : "=r"(r0), "=r"(r1), "=r"(r2), "=r"(r3) : "r"(addr));
}

__device__ __forceinline__ void mma_fp16(float* c, const uint32_t* a,
                                         uint32_t b0, uint32_t b1) {
    asm volatile(
        "mma.sync.aligned.m16n8k16.row.col.f32.f16.f16.f32 "
        "{%0,%1,%2,%3}, {%4,%5,%6,%7}, {%8,%9}, {%0,%1,%2,%3};"
        : "+f"(c[0]), "+f"(c[1]), "+f"(c[2]), "+f"(c[3])
        : "r"(a[0]), "r"(a[1]), "r"(a[2]), "r"(a[3]), "r"(b0), "r"(b1));
}

// ---------------------------------------------------------------------------
// Conversion: A(fp32) -> fp16, W(fp32) -> fp16
// ---------------------------------------------------------------------------
#define N4_A ((size_t)M_TOT * K_TOT / 4)
#define N4_W ((size_t)N_TOT * K_TOT / 4)
#define N4_TOTAL (N4_A + N4_W)

__global__ __launch_bounds__(256) void convert_kernel(
    const float* __restrict__ A, const float* __restrict__ W)
{
    size_t idx = (size_t)blockIdx.x * blockDim.x + threadIdx.x;
    if (idx >= N4_TOTAL) return;

    if (idx < N4_A) {
        float4 v = ((const float4*)A)[idx];
        __half h[4] = { __float2half_rn(v.x), __float2half_rn(v.y),
                        __float2half_rn(v.z), __float2half_rn(v.w) };
        *(uint2*)(g_ah + idx * 4) = *(uint2*)h;
    } else {
        size_t j = idx - N4_A;
        float4 v = ((const float4*)W)[j];
        __half h[4] = { __float2half_rn(v.x), __float2half_rn(v.y),
                        __float2half_rn(v.z), __float2half_rn(v.w) };
        *(uint2*)(g_wh + j * 4) = *(uint2*)h;
    }
}

// ---------------------------------------------------------------------------
// GEMM fp16 single-pass: qkv[m,n] = sum_k A[m,k]*W[n,k] + bias[n]
// CTA 128x128, BK=32, 4-stage cp.async, 2 CTAs/SM, fp16 output.
// ---------------------------------------------------------------------------
#define BK      32
#define KITERS  (K_TOT / BK)     // 32
#define STAGES  4
#define ROWB    80
#define TILEB   (128 * ROWB)     // 10240
#define STAGEB  (2 * TILEB)      // 20480 (Ah, Wh)
#define GEMM_SMEM (STAGES * STAGEB)  // 81920 -> 2 CTAs/SM

__global__ void __launch_bounds__(256, 2) gemm_qkv_mma(
    const __half* __restrict__ Ah, const __half* __restrict__ Wh,
    const float* __restrict__ bias, __half* __restrict__ C)
{
    extern __shared__ char smem[];
    const uint32_t sb = smem_u32(smem);
    const int t    = threadIdx.x;
    const int wid  = t >> 5;
    const int lane = t & 31;
    const int m0 = blockIdx.y * 128;
    const int n0 = blockIdx.x * 128;
    const int wm = (wid & 1) * 64;
    const int wn = (wid >> 1) * 32;

    // cp.async mapping: 4 x 16B chunks per thread per stage (2 tiles x 2 halves)
    const char* gptr[4];
    uint32_t    soff[4];
#pragma unroll
    for (int i = 0; i < 4; i++) {
        const int tile = i >> 1;            // 0=Ah, 1=Wh
        const int row  = (i & 1) * 64 + (t >> 2);
        const int c    = t & 3;
        const __half* base = (tile == 0) ? Ah : Wh;
        const int grow = ((tile == 0) ? m0 : n0) + row;
        gptr[i] = (const char*)(base + (size_t)grow * K_TOT) + c * 16;
        soff[i] = (uint32_t)(tile * TILEB + row * ROWB + c * 16);
    }

    auto load_stage = [&](int s) {
        const uint32_t dst = sb + (s % STAGES) * STAGEB;
        const int koff = s * (BK * 2);
#pragma unroll
        for (int i = 0; i < 4; i++)
            cp_async16(dst + soff[i], gptr[i] + koff);
    };

    float acc[4][4][4];
#pragma unroll
    for (int mt = 0; mt < 4; mt++)
#pragma unroll
        for (int nt = 0; nt < 4; nt++)
#pragma unroll
            for (int q = 0; q < 4; q++) acc[mt][nt][q] = 0.0f;

#pragma unroll
    for (int s = 0; s < STAGES - 1; s++) {
        load_stage(s);
        asm volatile("cp.async.commit_group;" ::: "memory");
    }

    const int lrow  = lane & 15;
    const int lkoff = (lane >> 4) * 16;

    for (int kit = 0; kit < KITERS; kit++) {
        asm volatile("cp.async.wait_group %0;" :: "n"(STAGES - 2) : "memory");
        __syncthreads();

        if (kit + STAGES - 1 < KITERS) load_stage(kit + STAGES - 1);
        asm volatile("cp.async.commit_group;" ::: "memory");

        const uint32_t bufb = sb + (kit % STAGES) * STAGEB;
        const uint32_t aH = bufb;
        const uint32_t wH = bufb + TILEB;

#pragma unroll
        for (int ks = 0; ks < 2; ks++) {
            const uint32_t kb = (uint32_t)(ks * 32 + lkoff);

            uint32_t af[4][4];
#pragma unroll
            for (int mt = 0; mt < 4; mt++) {
                const uint32_t ro = (uint32_t)((wm + mt * 16 + lrow) * ROWB) + kb;
                ldsm_x4(af[mt][0], af[mt][1], af[mt][2], af[mt][3], aH + ro);
            }

            uint32_t bh0[4], bh1[4];
#pragma unroll
            for (int np = 0; np < 2; np++) {
                const uint32_t ro = (uint32_t)((wn + np * 16 + lrow) * ROWB) + kb;
                uint32_t r0, r1, r2, r3;
                ldsm_x4(r0, r1, r2, r3, wH + ro);
                bh0[np * 2] = r0; bh1[np * 2] = r2;
                bh0[np * 2 + 1] = r1; bh1[np * 2 + 1] = r3;
            }

#pragma unroll
            for (int mt = 0; mt < 4; mt++)
#pragma unroll
                for (int nt = 0; nt < 4; nt++)
                    mma_fp16(acc[mt][nt], af[mt], bh0[nt], bh1[nt]);
        }
    }

    // Epilogue: bias add + fp16 store
#pragma unroll
    for (int mt = 0; mt < 4; mt++) {
        const int r = m0 + wm + mt * 16 + (lane >> 2);
#pragma unroll
        for (int nt = 0; nt < 4; nt++) {
            const int cc = n0 + wn + nt * 8 + (lane & 3) * 2;
            const float bx = __ldg(bias + cc);
            const float by = __ldg(bias + cc + 1);
            __half2 h0, h1;
            h0.x = __float2half_rn(acc[mt][nt][0] + bx);
            h0.y = __float2half_rn(acc[mt][nt][1] + by);
            h1.x = __float2half_rn(acc[mt][nt][2] + bx);
            h1.y = __float2half_rn(acc[mt][nt][3] + by);
            *(__half2*)(C + (size_t)r * N_TOT + cc)       = h0;
            *(__half2*)(C + (size_t)(r + 8) * N_TOT + cc) = h1;
        }
    }
}

// ---------------------------------------------------------------------------
// Attention: WARP-per-position. 128-thr blocks = 4 positions. No block syncs.
// ---------------------------------------------------------------------------
__global__ __launch_bounds__(128) void attn_kernel(
    const __half* __restrict__ qkv, const float* __restrict__ mask,
    float* __restrict__ out)
{
    __shared__ __align__(16) unsigned char sm[4][8000];

    const int wid  = threadIdx.x >> 5;
    const int lane = threadIdx.x & 31;
    const int p = blockIdx.x * 4 + wid;

    __half* sqkv = (__half*)sm[wid];                 // arr*1152 + h*72 + d
    float*  sw   = (float*)(sm[wid] + 6912);         // [16][17]

    // Load 3072 halfs = 384 uint4; 12 per lane
    {
        const uint4* src = (const uint4*)(qkv + (size_t)p * N_TOT);
#pragma unroll
        for (int i = lane; i < 384; i += 32) {
            uint4 raw = src[i];
            const int e = i * 8;
            const int arr = e >> 10;          // 0=q, 1=k, 2=v
            const int r   = e & 1023;
            *(uint4*)(sqkv + arr * 1152 + (r >> 6) * 72 + (r & 63)) = raw;
        }
    }
    __syncwarp();

    const int h  = lane >> 1;
    const int gh = lane & 1;

    // ---- QK: 8 dot products of length 64 ----
    float s[8];
#pragma unroll
    for (int gi = 0; gi < 8; gi++) s[gi] = 0.0f;

    const __half* qrow = sqkv + h * 72;
#pragma unroll
    for (int d8 = 0; d8 < 8; d8++) {
        uint4 qraw = *(const uint4*)(qrow + d8 * 8);
        const __half2* qh2 = (const __half2*)&qraw;
        float qf[8];
#pragma unroll
        for (int j = 0; j < 4; j++) {
            float2 f = __half22float2(qh2[j]);
            qf[2 * j] = f.x; qf[2 * j + 1] = f.y;
        }
#pragma unroll
        for (int gi = 0; gi < 8; gi++) {
            const __half* krow = sqkv + 1152 + (gh * 8 + gi) * 72;
            uint4 kraw = *(const uint4*)(krow + d8 * 8);
            const __half2* kh2 = (const __half2*)&kraw;
#pragma unroll
            for (int j = 0; j < 4; j++) {
                float2 f = __half22float2(kh2[j]);
                s[gi] += qf[2 * j] * f.x + qf[2 * j + 1] * f.y;
            }
        }
    }

    // scale + mask
    {
        const float* mrow = mask + (size_t)p * (NH * NH) + h * NH + gh * 8;
        float4 m0 = *(const float4*)mrow;
        float4 m1 = *(const float4*)(mrow + 4);
        const float mf[8] = {m0.x, m0.y, m0.z, m0.w, m1.x, m1.y, m1.z, m1.w};
#pragma unroll
        for (int gi = 0; gi < 8; gi++) s[gi] = s[gi] * 0.125f + mf[gi];
    }

    // ---- softmax across the 16-wide row (2 lanes per row) ----
    float mx = s[0];
#pragma unroll
    for (int gi = 1; gi < 8; gi++) mx = fmaxf(mx, s[gi]);
    mx = fmaxf(mx, __shfl_xor_sync(0xffffffff, mx, 1));

    float e[8], sum = 0.0f;
#pragma unroll
    for (int gi = 0; gi < 8; gi++) { e[gi] = __expf(s[gi] - mx); sum += e[gi]; }
    sum += __shfl_xor_sync(0xffffffff, sum, 1);
    const float inv = 1.0f / sum;

#pragma unroll
    for (int gi = 0; gi < 8; gi++) sw[h * 17 + gh * 8 + gi] = e[gi] * inv;
    __syncwarp();

    // ---- PV: lane computes out[h][gh*32 .. gh*32+31] ----
    float acc[32];
#pragma unroll
    for (int d = 0; d < 32; d++) acc[d] = 0.0f;

#pragma unroll
    for (int g = 0; g < 16; g++) {
        const float wv = sw[h * 17 + g];
        const __half* vrow = sqkv + 2304 + g * 72 + gh * 32;
#pragma unroll
        for (int d8 = 0; d8 < 4; d8++) {
            uint4 vr = *(const uint4*)(vrow + d8 * 8);
            const __half2* vh2 = (const __half2*)&vr;
#pragma unroll
            for (int j = 0; j < 4; j++) {
                float2 f = __half22float2(vh2[j]);
                acc[d8 * 8 + 2 * j]     += wv * f.x;
                acc[d8 * 8 + 2 * j + 1] += wv * f.y;
            }
        }
    }

    float* orow = out + (size_t)p * HID + h * DH + gh * 32;
#pragma unroll
    for (int d4 = 0; d4 < 8; d4++) {
        float4 o;
        o.x = acc[4 * d4]; o.y = acc[4 * d4 + 1];
        o.z = acc[4 * d4 + 2]; o.w = acc[4 * d4 + 3];
        *(float4*)(orow + 4 * d4) = o;
    }
}

// ---------------------------------------------------------------------------
// Launch — inputs: 0=query, 1=key, 2=value, 3=attn_mask, 4=W_qkv, 5=b_qkv
// ---------------------------------------------------------------------------
extern "C" void kernel_launch(void* const* d_in, const int* in_sizes, int n_in,
                              void* d_out, int out_size)
{
    const float* query = (const float*)d_in[0];
    const float* mask  = (const float*)d_in[3];
    const float* W     = (const float*)d_in[4];
    const float* bias  = (const float*)d_in[5];
    float* out = (float*)d_out;

    __half *qkv, *ah, *wh;
    cudaGetSymbolAddress((void**)&qkv, g_qkv);
    cudaGetSymbolAddress((void**)&ah, g_ah);
    cudaGetSymbolAddress((void**)&wh, g_wh);

    const int cvt_blocks = (int)((N4_TOTAL + 255) / 256);
    convert_kernel<<<cvt_blocks, 256>>>(query, W);

    cudaFuncSetAttribute(gemm_qkv_mma, cudaFuncAttributeMaxDynamicSharedMemorySize,
                         GEMM_SMEM);
    dim3 ggrid(N_TOT / 128, M_TOT / 128);  // (24, 128)
    gemm_qkv_mma<<<ggrid, 256, GEMM_SMEM>>>(ah, wh, bias, qkv);

    attn_kernel<<<M_TOT / 4, 128>>>(qkv, mask, out);
}